// round 2
// baseline (speedup 1.0000x reference)
#include <cuda_runtime.h>
#include <math.h>

// Problem constants
static const int cB = 64;
static const int cM = 512;
static const int cD = 2048;
static const int cK = 32;
static const int cBM = cB * cM;          // 32768

// Scratch (device globals; no allocation allowed)
__device__ float g_sb[cBM * cK];         // sa * inv_norm, [b,m,k]   (4 MB)
__device__ float g_colsum[cB * cK];      // sum_m sa
__device__ float g_nrmsq[cB * cK];       // per-(b,k) sum of vlad^2
__device__ float g_factor[cB * cK];      // final scale per (b,k)

// ---------------------------------------------------------------------------
// init: zero the accumulators (must happen every replay)
// ---------------------------------------------------------------------------
__global__ void init_kernel() {
    int t = blockIdx.x * blockDim.x + threadIdx.x;
    if (t < cB * cK) {
        g_colsum[t] = 0.0f;
        g_nrmsq[t]  = 0.0f;
    }
}

// ---------------------------------------------------------------------------
// Kernel L: logits GEMM [BM,2048]x[2048,32] + row-norm + softmax + sb + colsum
// Block: 256 threads, TM=128 rows (one b per block since 128 | 512).
// Thread tile: 4m x 4k. Shared tiles transposed for float4 inner loads.
// ---------------------------------------------------------------------------
#define L_TM 128
#define L_DC 32

__global__ __launch_bounds__(256) void logits_kernel(
    const float* __restrict__ x, const float* __restrict__ Wm)
{
    __shared__ float xs[L_DC][L_TM + 4];   // stride 132 (16B aligned)
    __shared__ float ws[L_DC][cK + 4];     // stride 36
    __shared__ float rowsq[L_TM];

    const int t    = threadIdx.x;
    const int bm0  = blockIdx.x * L_TM;
    const int b    = bm0 / cM;
    const int lane = t & 31;
    const int w    = t >> 5;               // warp id 0..7
    const int kg   = t & 7;
    const int mg   = t >> 3;               // 0..31
    const int m4   = mg * 4;
    const int k4   = kg * 4;
    const int dd   = lane;                 // load column within chunk

    float acc[4][4];
#pragma unroll
    for (int i = 0; i < 4; i++)
#pragma unroll
        for (int j = 0; j < 4; j++) acc[i][j] = 0.0f;

    float psq[16];                          // per-thread sumsq partials (m = w + 8*j)
#pragma unroll
    for (int j = 0; j < 16; j++) psq[j] = 0.0f;

    for (int d0 = 0; d0 < cD; d0 += L_DC) {
        // load x tile (transposed) + accumulate sumsq partials
#pragma unroll
        for (int j = 0; j < 16; j++) {
            int m = w + 8 * j;
            float v = x[(bm0 + m) * cD + d0 + dd];
            xs[dd][m] = v;
            psq[j] += v * v;
        }
        // load W tile (transposed)
#pragma unroll
        for (int j = 0; j < 4; j++) {
            int k = w + 8 * j;
            ws[dd][k] = Wm[k * cD + d0 + dd];
        }
        __syncthreads();

#pragma unroll 8
        for (int dj = 0; dj < L_DC; dj++) {
            float4 xv = *(const float4*)&xs[dj][m4];
            float4 wv = *(const float4*)&ws[dj][k4];
            float xa[4] = {xv.x, xv.y, xv.z, xv.w};
            float wa[4] = {wv.x, wv.y, wv.z, wv.w};
#pragma unroll
            for (int i = 0; i < 4; i++)
#pragma unroll
                for (int j = 0; j < 4; j++) acc[i][j] += xa[i] * wa[j];
        }
        __syncthreads();
    }

    // reduce sumsq partials: warp w owns rows m = w + 8*j
#pragma unroll
    for (int j = 0; j < 16; j++) {
        float v = psq[j];
#pragma unroll
        for (int o = 16; o; o >>= 1) v += __shfl_xor_sync(0xFFFFFFFFu, v, o);
        if (lane == 0) rowsq[w + 8 * j] = v;
    }
    __syncthreads();

    // softmax over k per row; rows split across 8 lanes (k-groups)
    float cs[4] = {0.f, 0.f, 0.f, 0.f};
#pragma unroll
    for (int i = 0; i < 4; i++) {
        float nrm = sqrtf(rowsq[m4 + i]);
        float inv = 1.0f / fmaxf(nrm, 1e-12f);
        float l[4];
        float mx = -1e30f;
#pragma unroll
        for (int j = 0; j < 4; j++) { l[j] = acc[i][j] * inv; mx = fmaxf(mx, l[j]); }
#pragma unroll
        for (int o = 1; o < 8; o <<= 1) mx = fmaxf(mx, __shfl_xor_sync(0xFFFFFFFFu, mx, o));
        float s = 0.0f;
#pragma unroll
        for (int j = 0; j < 4; j++) { l[j] = __expf(l[j] - mx); s += l[j]; }
#pragma unroll
        for (int o = 1; o < 8; o <<= 1) s += __shfl_xor_sync(0xFFFFFFFFu, s, o);
        float isr = 1.0f / s;
        float4 sb;
        float sa0 = l[0] * isr, sa1 = l[1] * isr, sa2 = l[2] * isr, sa3 = l[3] * isr;
        cs[0] += sa0; cs[1] += sa1; cs[2] += sa2; cs[3] += sa3;
        sb.x = sa0 * inv; sb.y = sa1 * inv; sb.z = sa2 * inv; sb.w = sa3 * inv;
        *(float4*)&g_sb[(bm0 + m4 + i) * cK + k4] = sb;
    }

    // colsum: reduce over the warp's 4 m-groups, then atomic
#pragma unroll
    for (int j = 0; j < 4; j++) {
        float v = cs[j];
        v += __shfl_xor_sync(0xFFFFFFFFu, v, 8);
        v += __shfl_xor_sync(0xFFFFFFFFu, v, 16);
        if ((lane & 24) == 0) atomicAdd(&g_colsum[b * cK + k4 + j], v);
    }
}

// ---------------------------------------------------------------------------
// Kernel G: agg[b] = sb[b]^T @ x[b]  ([32,512] x [512,2048]), epilogue:
// vlad = agg - colsum*centroid, write to out, accumulate per-(b,k) sumsq.
// Grid: b (64) x d-chunk (16 of 128). Block 256 threads, thread tile 4k x 4d.
// ---------------------------------------------------------------------------
#define G_DN 128
#define G_MT 32

__global__ __launch_bounds__(256) void agg_kernel(
    const float* __restrict__ x, const float* __restrict__ cent,
    float* __restrict__ out)
{
    __shared__ float sbs[G_MT][cK + 4];    // stride 36
    __shared__ float xt[G_MT][G_DN];       // stride 128

    const int t  = threadIdx.x;
    const int b  = blockIdx.x >> 4;
    const int d0 = (blockIdx.x & 15) * G_DN;
    const int lane = t & 31;
    const int kg = t & 7;
    const int dg = t >> 3;                 // 0..31
    const int k4 = kg * 4;
    const int d4 = dg * 4;

    float acc[4][4];
#pragma unroll
    for (int i = 0; i < 4; i++)
#pragma unroll
        for (int j = 0; j < 4; j++) acc[i][j] = 0.0f;

    const int skk = t & 31, smm = t >> 5;     // sb loader
    const int xdl = t & 127, xmm = t >> 7;    // x loader

    for (int m0 = 0; m0 < cM; m0 += G_MT) {
#pragma unroll
        for (int j = 0; j < 4; j++) {
            int mmr = smm + 8 * j;
            sbs[mmr][skk] = g_sb[(b * cM + m0 + mmr) * cK + skk];
        }
#pragma unroll
        for (int j = 0; j < 16; j++) {
            int mmr = xmm + 2 * j;
            xt[mmr][xdl] = x[(b * cM + m0 + mmr) * cD + d0 + xdl];
        }
        __syncthreads();

#pragma unroll 8
        for (int mm = 0; mm < G_MT; mm++) {
            float4 sv = *(const float4*)&sbs[mm][k4];
            float4 xv = *(const float4*)&xt[mm][d4];
            float sa[4] = {sv.x, sv.y, sv.z, sv.w};
            float xa[4] = {xv.x, xv.y, xv.z, xv.w};
#pragma unroll
            for (int i = 0; i < 4; i++)
#pragma unroll
                for (int j = 0; j < 4; j++) acc[i][j] += sa[i] * xa[j];
        }
        __syncthreads();
    }

    // epilogue
    float ssq[4];
#pragma unroll
    for (int i = 0; i < 4; i++) {
        int k = k4 + i;
        float csk = g_colsum[b * cK + k];
        float4 cv = *(const float4*)&cent[k * cD + d0 + d4];
        float4 o;
        o.x = acc[i][0] - csk * cv.x;
        o.y = acc[i][1] - csk * cv.y;
        o.z = acc[i][2] - csk * cv.z;
        o.w = acc[i][3] - csk * cv.w;
        ssq[i] = o.x * o.x + o.y * o.y + o.z * o.z + o.w * o.w;
        *(float4*)&out[b * (cK * cD) + k * cD + d0 + d4] = o;
    }
#pragma unroll
    for (int i = 0; i < 4; i++) {
        float v = ssq[i];
        v += __shfl_xor_sync(0xFFFFFFFFu, v, 8);
        v += __shfl_xor_sync(0xFFFFFFFFu, v, 16);
        if ((lane & 24) == 0) atomicAdd(&g_nrmsq[b * cK + k4 + i], v);
    }
}

// ---------------------------------------------------------------------------
// F1: per-(b,k) final scale = 1/(max(||v_k||,eps) * max(||flat intra-norm||,eps))
// ---------------------------------------------------------------------------
__global__ void factor_kernel() {
    int b = blockIdx.x;
    int k = threadIdx.x;   // 32 threads
    float nsq = g_nrmsq[b * cK + k];
    float n   = sqrtf(nsq);
    float dn  = fmaxf(n, 1e-12f);
    float r   = n / dn;
    float g2  = r * r;
#pragma unroll
    for (int o = 1; o < 32; o <<= 1) g2 += __shfl_xor_sync(0xFFFFFFFFu, g2, o);
    float g = sqrtf(g2);
    g_factor[b * cK + k] = 1.0f / (dn * fmaxf(g, 1e-12f));
}

// ---------------------------------------------------------------------------
// F2: in-place scale of out by per-(b,k) factor
// ---------------------------------------------------------------------------
__global__ __launch_bounds__(256) void scale_kernel(float* __restrict__ out) {
    int i = blockIdx.x * 256 + threadIdx.x;   // float4 index; total 1048576
    float4* o4 = (float4*)out;
    float f = g_factor[i >> 9];               // 512 float4 per (b,k)
    float4 v = o4[i];
    v.x *= f; v.y *= f; v.z *= f; v.w *= f;
    o4[i] = v;
}

// ---------------------------------------------------------------------------
extern "C" void kernel_launch(void* const* d_in, const int* in_sizes, int n_in,
                              void* d_out, int out_size) {
    const float* x    = (const float*)d_in[0];
    const float* Wm   = (const float*)d_in[1];
    const float* cent = (const float*)d_in[2];
    float* out        = (float*)d_out;

    init_kernel<<<8, 256>>>();
    logits_kernel<<<cBM / L_TM, 256>>>(x, Wm);
    agg_kernel<<<cB * 16, 256>>>(x, cent, out);
    factor_kernel<<<cB, 32>>>();
    scale_kernel<<<(cB * cK * cD / 4) / 256, 256>>>(out);
}

// round 4
// speedup vs baseline: 1.0009x; 1.0009x over previous
#include <cuda_runtime.h>
#include <math.h>

// Problem constants
static const int cB = 64;
static const int cM = 512;
static const int cD = 2048;
static const int cK = 32;
static const int cBM = cB * cM;          // 32768

// Scratch (device globals; no allocation allowed)
__device__ float g_sb[cBM * cK];         // sa * inv_norm, [b,m,k]   (4 MB)
__device__ float g_colsum[cB * cK];      // sum_m sa
__device__ float g_nrmsq[cB * cK];       // per-(b,k) sum of vlad^2
__device__ float g_factor[cB * cK];      // final scale per (b,k)

// ---------------------------------------------------------------------------
// init: zero the accumulators (must happen every replay)
// ---------------------------------------------------------------------------
__global__ void init_kernel() {
    int t = blockIdx.x * blockDim.x + threadIdx.x;
    if (t < cB * cK) {
        g_colsum[t] = 0.0f;
        g_nrmsq[t]  = 0.0f;
    }
}

// ---------------------------------------------------------------------------
// Kernel L: logits GEMM [BM,2048]x[2048,32] + row-norm + softmax + sb + colsum
// Block: 256 threads, TM=128 rows (one b per block since 128 | 512).
// Thread tile: 4m x 4k. Shared tiles transposed for float4 inner loads.
// ---------------------------------------------------------------------------
#define L_TM 128
#define L_DC 32

__global__ __launch_bounds__(256) void logits_kernel(
    const float* __restrict__ x, const float* __restrict__ Wm)
{
    __shared__ float xs[L_DC][L_TM + 4];   // stride 132 (16B aligned)
    __shared__ float ws[L_DC][cK + 4];     // stride 36
    __shared__ float rowsq[L_TM];

    const int t    = threadIdx.x;
    const int bm0  = blockIdx.x * L_TM;
    const int b    = bm0 / cM;
    const int lane = t & 31;
    const int w    = t >> 5;               // warp id 0..7
    const int kg   = t & 7;
    const int mg   = t >> 3;               // 0..31
    const int m4   = mg * 4;
    const int k4   = kg * 4;
    const int dd   = lane;                 // load column within chunk

    float acc[4][4];
#pragma unroll
    for (int i = 0; i < 4; i++)
#pragma unroll
        for (int j = 0; j < 4; j++) acc[i][j] = 0.0f;

    float psq[16];                          // per-thread sumsq partials (m = w + 8*j)
#pragma unroll
    for (int j = 0; j < 16; j++) psq[j] = 0.0f;

    for (int d0 = 0; d0 < cD; d0 += L_DC) {
        // load x tile (transposed) + accumulate sumsq partials
#pragma unroll
        for (int j = 0; j < 16; j++) {
            int m = w + 8 * j;
            float v = x[(bm0 + m) * cD + d0 + dd];
            xs[dd][m] = v;
            psq[j] += v * v;
        }
        // load W tile (transposed)
#pragma unroll
        for (int j = 0; j < 4; j++) {
            int k = w + 8 * j;
            ws[dd][k] = Wm[k * cD + d0 + dd];
        }
        __syncthreads();

#pragma unroll 8
        for (int dj = 0; dj < L_DC; dj++) {
            float4 xv = *(const float4*)&xs[dj][m4];
            float4 wv = *(const float4*)&ws[dj][k4];
            float xa[4] = {xv.x, xv.y, xv.z, xv.w};
            float wa[4] = {wv.x, wv.y, wv.z, wv.w};
#pragma unroll
            for (int i = 0; i < 4; i++)
#pragma unroll
                for (int j = 0; j < 4; j++) acc[i][j] += xa[i] * wa[j];
        }
        __syncthreads();
    }

    // reduce sumsq partials: warp w owns rows m = w + 8*j
#pragma unroll
    for (int j = 0; j < 16; j++) {
        float v = psq[j];
#pragma unroll
        for (int o = 16; o; o >>= 1) v += __shfl_xor_sync(0xFFFFFFFFu, v, o);
        if (lane == 0) rowsq[w + 8 * j] = v;
    }
    __syncthreads();

    // softmax over k per row; rows split across 8 lanes (k-groups)
    float cs[4] = {0.f, 0.f, 0.f, 0.f};
#pragma unroll
    for (int i = 0; i < 4; i++) {
        float nrm = sqrtf(rowsq[m4 + i]);
        float inv = 1.0f / fmaxf(nrm, 1e-12f);
        float l[4];
        float mx = -1e30f;
#pragma unroll
        for (int j = 0; j < 4; j++) { l[j] = acc[i][j] * inv; mx = fmaxf(mx, l[j]); }
#pragma unroll
        for (int o = 1; o < 8; o <<= 1) mx = fmaxf(mx, __shfl_xor_sync(0xFFFFFFFFu, mx, o));
        float s = 0.0f;
#pragma unroll
        for (int j = 0; j < 4; j++) { l[j] = __expf(l[j] - mx); s += l[j]; }
#pragma unroll
        for (int o = 1; o < 8; o <<= 1) s += __shfl_xor_sync(0xFFFFFFFFu, s, o);
        float isr = 1.0f / s;
        float4 sb;
        float sa0 = l[0] * isr, sa1 = l[1] * isr, sa2 = l[2] * isr, sa3 = l[3] * isr;
        cs[0] += sa0; cs[1] += sa1; cs[2] += sa2; cs[3] += sa3;
        sb.x = sa0 * inv; sb.y = sa1 * inv; sb.z = sa2 * inv; sb.w = sa3 * inv;
        *(float4*)&g_sb[(bm0 + m4 + i) * cK + k4] = sb;
    }

    // colsum: reduce over the warp's 4 m-groups, then atomic
#pragma unroll
    for (int j = 0; j < 4; j++) {
        float v = cs[j];
        v += __shfl_xor_sync(0xFFFFFFFFu, v, 8);
        v += __shfl_xor_sync(0xFFFFFFFFu, v, 16);
        if ((lane & 24) == 0) atomicAdd(&g_colsum[b * cK + k4 + j], v);
    }
}

// ---------------------------------------------------------------------------
// Kernel G: agg[b] = sb[b]^T @ x[b]  ([32,512] x [512,2048]), epilogue:
// vlad = agg - colsum*centroid, write to out, accumulate per-(b,k) sumsq.
// Grid: b (64) x d-chunk (16 of 128). Block 256 threads, thread tile 4k x 4d.
// ---------------------------------------------------------------------------
#define G_DN 128
#define G_MT 32

__global__ __launch_bounds__(256) void agg_kernel(
    const float* __restrict__ x, const float* __restrict__ cent,
    float* __restrict__ out)
{
    __shared__ float sbs[G_MT][cK + 4];    // stride 36
    __shared__ float xt[G_MT][G_DN];       // stride 128

    const int t  = threadIdx.x;
    const int b  = blockIdx.x >> 4;
    const int d0 = (blockIdx.x & 15) * G_DN;
    const int lane = t & 31;
    const int kg = t & 7;
    const int dg = t >> 3;                 // 0..31
    const int k4 = kg * 4;
    const int d4 = dg * 4;

    float acc[4][4];
#pragma unroll
    for (int i = 0; i < 4; i++)
#pragma unroll
        for (int j = 0; j < 4; j++) acc[i][j] = 0.0f;

    const int skk = t & 31, smm = t >> 5;     // sb loader
    const int xdl = t & 127, xmm = t >> 7;    // x loader

    for (int m0 = 0; m0 < cM; m0 += G_MT) {
#pragma unroll
        for (int j = 0; j < 4; j++) {
            int mmr = smm + 8 * j;
            sbs[mmr][skk] = g_sb[(b * cM + m0 + mmr) * cK + skk];
        }
#pragma unroll
        for (int j = 0; j < 16; j++) {
            int mmr = xmm + 2 * j;
            xt[mmr][xdl] = x[(b * cM + m0 + mmr) * cD + d0 + xdl];
        }
        __syncthreads();

#pragma unroll 8
        for (int mm = 0; mm < G_MT; mm++) {
            float4 sv = *(const float4*)&sbs[mm][k4];
            float4 xv = *(const float4*)&xt[mm][d4];
            float sa[4] = {sv.x, sv.y, sv.z, sv.w};
            float xa[4] = {xv.x, xv.y, xv.z, xv.w};
#pragma unroll
            for (int i = 0; i < 4; i++)
#pragma unroll
                for (int j = 0; j < 4; j++) acc[i][j] += sa[i] * xa[j];
        }
        __syncthreads();
    }

    // epilogue
    float ssq[4];
#pragma unroll
    for (int i = 0; i < 4; i++) {
        int k = k4 + i;
        float csk = g_colsum[b * cK + k];
        float4 cv = *(const float4*)&cent[k * cD + d0 + d4];
        float4 o;
        o.x = acc[i][0] - csk * cv.x;
        o.y = acc[i][1] - csk * cv.y;
        o.z = acc[i][2] - csk * cv.z;
        o.w = acc[i][3] - csk * cv.w;
        ssq[i] = o.x * o.x + o.y * o.y + o.z * o.z + o.w * o.w;
        *(float4*)&out[b * (cK * cD) + k * cD + d0 + d4] = o;
    }
#pragma unroll
    for (int i = 0; i < 4; i++) {
        float v = ssq[i];
        v += __shfl_xor_sync(0xFFFFFFFFu, v, 8);
        v += __shfl_xor_sync(0xFFFFFFFFu, v, 16);
        if ((lane & 24) == 0) atomicAdd(&g_nrmsq[b * cK + k4 + i], v);
    }
}

// ---------------------------------------------------------------------------
// F1: per-(b,k) final scale = 1/(max(||v_k||,eps) * max(||flat intra-norm||,eps))
// ---------------------------------------------------------------------------
__global__ void factor_kernel() {
    int b = blockIdx.x;
    int k = threadIdx.x;   // 32 threads
    float nsq = g_nrmsq[b * cK + k];
    float n   = sqrtf(nsq);
    float dn  = fmaxf(n, 1e-12f);
    float r   = n / dn;
    float g2  = r * r;
#pragma unroll
    for (int o = 1; o < 32; o <<= 1) g2 += __shfl_xor_sync(0xFFFFFFFFu, g2, o);
    float g = sqrtf(g2);
    g_factor[b * cK + k] = 1.0f / (dn * fmaxf(g, 1e-12f));
}

// ---------------------------------------------------------------------------
// F2: in-place scale of out by per-(b,k) factor
// ---------------------------------------------------------------------------
__global__ __launch_bounds__(256) void scale_kernel(float* __restrict__ out) {
    int i = blockIdx.x * 256 + threadIdx.x;   // float4 index; total 1048576
    float4* o4 = (float4*)out;
    float f = g_factor[i >> 9];               // 512 float4 per (b,k)
    float4 v = o4[i];
    v.x *= f; v.y *= f; v.z *= f; v.w *= f;
    o4[i] = v;
}

// ---------------------------------------------------------------------------
extern "C" void kernel_launch(void* const* d_in, const int* in_sizes, int n_in,
                              void* d_out, int out_size) {
    const float* x    = (const float*)d_in[0];
    const float* Wm   = (const float*)d_in[1];
    const float* cent = (const float*)d_in[2];
    float* out        = (float*)d_out;

    init_kernel<<<8, 256>>>();
    logits_kernel<<<cBM / L_TM, 256>>>(x, Wm);
    agg_kernel<<<cB * 16, 256>>>(x, cent, out);
    factor_kernel<<<cB, 32>>>();
    scale_kernel<<<(cB * cK * cD / 4) / 256, 256>>>(out);
}

// round 6
// speedup vs baseline: 1.6910x; 1.6894x over previous
#include <cuda_runtime.h>
#include <cuda_bf16.h>
#include <math.h>
#include <stdint.h>

// Problem constants
static const int cB = 64;
static const int cM = 512;
static const int cD = 2048;
static const int cK = 32;
static const int cBM = cB * cM;          // 32768

// Scratch (device globals; no allocation allowed)
__device__ float g_sb[cBM * cK];         // sa * inv_norm, [b,m,k]   (4 MB)
__device__ float g_colsum[cB * cK];      // sum_m sa
__device__ float g_nrmsq[cB * cK];       // per-(b,k) sum of vlad^2
__device__ float g_factor[cB * cK];      // final scale per (b,k)

// ---------------------------------------------------------------------------
// helpers
// ---------------------------------------------------------------------------
__device__ __forceinline__ uint32_t s2u(const void* p) {
    return (uint32_t)__cvta_generic_to_shared(p);
}

__device__ __forceinline__ void ldmx4(uint32_t* r, uint32_t a) {
    asm volatile("ldmatrix.sync.aligned.m8n8.x4.shared.b16 {%0,%1,%2,%3},[%4];"
        : "=r"(r[0]), "=r"(r[1]), "=r"(r[2]), "=r"(r[3]) : "r"(a));
}
__device__ __forceinline__ void ldmx4t(uint32_t* r, uint32_t a) {
    asm volatile("ldmatrix.sync.aligned.m8n8.x4.trans.shared.b16 {%0,%1,%2,%3},[%4];"
        : "=r"(r[0]), "=r"(r[1]), "=r"(r[2]), "=r"(r[3]) : "r"(a));
}
__device__ __forceinline__ void mma16816(float* c, const uint32_t* a,
                                         uint32_t b0, uint32_t b1) {
    asm volatile(
        "mma.sync.aligned.m16n8k16.row.col.f32.bf16.bf16.f32 "
        "{%0,%1,%2,%3},{%4,%5,%6,%7},{%8,%9},{%0,%1,%2,%3};"
        : "+f"(c[0]), "+f"(c[1]), "+f"(c[2]), "+f"(c[3])
        : "r"(a[0]), "r"(a[1]), "r"(a[2]), "r"(a[3]), "r"(b0), "r"(b1));
}

// split 8 fp32 into hi/lo bf16 16B units
__device__ __forceinline__ void split8(float4 a, float4 b, uint4& H, uint4& L) {
    float f[8] = {a.x, a.y, a.z, a.w, b.x, b.y, b.z, b.w};
    uint32_t h[4], l[4];
#pragma unroll
    for (int i = 0; i < 4; i++) {
        __nv_bfloat162 hh = __floats2bfloat162_rn(f[2*i], f[2*i+1]);
        float r0 = f[2*i]   - __low2float(hh);
        float r1 = f[2*i+1] - __high2float(hh);
        __nv_bfloat162 ll = __floats2bfloat162_rn(r0, r1);
        h[i] = *reinterpret_cast<uint32_t*>(&hh);
        l[i] = *reinterpret_cast<uint32_t*>(&ll);
    }
    H = make_uint4(h[0], h[1], h[2], h[3]);
    L = make_uint4(l[0], l[1], l[2], l[3]);
}

// ---------------------------------------------------------------------------
// init: zero the accumulators (must happen every replay)
// ---------------------------------------------------------------------------
__global__ void init_kernel() {
    int t = blockIdx.x * blockDim.x + threadIdx.x;
    if (t < cB * cK) {
        g_colsum[t] = 0.0f;
        g_nrmsq[t]  = 0.0f;
    }
}

// ---------------------------------------------------------------------------
// Kernel L: logits = (x @ W^T)*inv_norm, softmax, sb = sa*inv, colsum.
// Tensor-core version: bf16 hi/lo split, mma.sync m16n8k16.
// Block 256 thr (8 warps), tile M=128 rows x K=32 clusters, D chunk 64.
// Warp w owns m16 tile rows [16w,16w+16), all 32 n columns (4 n8 tiles).
// ---------------------------------------------------------------------------
__global__ __launch_bounds__(256) void logits_kernel(
    const float* __restrict__ x, const float* __restrict__ W)
{
    __shared__ __align__(16) __nv_bfloat16 As[2][128 * 64];  // hi/lo, swizzled
    __shared__ __align__(16) __nv_bfloat16 Ws[2][32 * 64];
    __shared__ float rowsq[128];
    __shared__ float colsum_s[32];

    const int t = threadIdx.x, lane = t & 31, w = t >> 5;
    const int bm0 = blockIdx.x * 128;
    const int b   = bm0 >> 9;
    if (t < 32) colsum_s[t] = 0.0f;

    float C[4][4];
#pragma unroll
    for (int i = 0; i < 4; i++)
#pragma unroll
        for (int j = 0; j < 4; j++) C[i][j] = 0.0f;
    float psq[4] = {0.f, 0.f, 0.f, 0.f};

    const int ar = t >> 3;       // conversion: row base (+32i), unit au
    const int au = t & 7;
    const int amr = 16 * w + (lane & 15);                 // A ldmatrix row
    const int bnr = (lane & 7) + ((lane >> 4) << 3);      // B ldmatrix n base

    for (int d0 = 0; d0 < 2048; d0 += 64) {
        // stage x tile -> hi/lo bf16 (swizzled), accumulate row sumsq
#pragma unroll
        for (int i = 0; i < 4; i++) {
            int r = ar + 32 * i;
            const float4* p = (const float4*)(x + (size_t)(bm0 + r) * 2048 + d0 + au * 8);
            float4 f0 = p[0], f1 = p[1];
            psq[i] += f0.x*f0.x + f0.y*f0.y + f0.z*f0.z + f0.w*f0.w
                    + f1.x*f1.x + f1.y*f1.y + f1.z*f1.z + f1.w*f1.w;
            uint4 H, L; split8(f0, f1, H, L);
            int off = r * 64 + ((au ^ (r & 7)) << 3);
            *(uint4*)&As[0][off] = H;
            *(uint4*)&As[1][off] = L;
        }
        {   // stage W tile
            int r = t >> 3, u = t & 7;
            const float4* p = (const float4*)(W + (size_t)r * 2048 + d0 + u * 8);
            float4 f0 = p[0], f1 = p[1];
            uint4 H, L; split8(f0, f1, H, L);
            int off = r * 64 + ((u ^ (r & 7)) << 3);
            *(uint4*)&Ws[0][off] = H;
            *(uint4*)&Ws[1][off] = L;
        }
        __syncthreads();

#pragma unroll
        for (int kk = 0; kk < 64; kk += 16) {
            uint32_t ah[4], al[4], bh[8], bl[8];
            int u = (kk >> 3) + (lane >> 4);
            int aoff = amr * 64 + ((u ^ (amr & 7)) << 3);
            ldmx4(ah, s2u(&As[0][aoff]));
            ldmx4(al, s2u(&As[1][aoff]));
            int ub = (kk >> 3) + ((lane >> 3) & 1);
#pragma unroll
            for (int half = 0; half < 2; half++) {
                int n = bnr + 16 * half;
                int boff = n * 64 + ((ub ^ (n & 7)) << 3);
                ldmx4(bh + 4 * half, s2u(&Ws[0][boff]));
                ldmx4(bl + 4 * half, s2u(&Ws[1][boff]));
            }
#pragma unroll
            for (int nt = 0; nt < 4; nt++) {
                mma16816(C[nt], ah, bh[2*nt], bh[2*nt+1]);   // hi*hi
                mma16816(C[nt], ah, bl[2*nt], bl[2*nt+1]);   // hi*lo
                mma16816(C[nt], al, bh[2*nt], bh[2*nt+1]);   // lo*hi
            }
        }
        __syncthreads();
    }

    // reduce sumsq: 8 lanes (same t>>3 group) share each row
#pragma unroll
    for (int i = 0; i < 4; i++) {
        float v = psq[i];
        v += __shfl_xor_sync(0xFFFFFFFFu, v, 1);
        v += __shfl_xor_sync(0xFFFFFFFFu, v, 2);
        v += __shfl_xor_sync(0xFFFFFFFFu, v, 4);
        if ((lane & 7) == 0) rowsq[(t >> 3) + 32 * i] = v;
    }
    __syncthreads();

    // softmax epilogue: thread holds rows 16w+g and +8, cols 8nt+2q(+1)
    const int g = lane >> 2, q = lane & 3;
    float csv[8];
#pragma unroll
    for (int i = 0; i < 8; i++) csv[i] = 0.0f;

#pragma unroll
    for (int idx = 0; idx < 2; idx++) {
        int r = 16 * w + g + 8 * idx;
        float inv = 1.0f / fmaxf(sqrtf(rowsq[r]), 1e-12f);
        float v[8];
#pragma unroll
        for (int nt = 0; nt < 4; nt++) {
            v[2*nt]   = C[nt][2*idx]   * inv;
            v[2*nt+1] = C[nt][2*idx+1] * inv;
        }
        float mx = v[0];
#pragma unroll
        for (int i = 1; i < 8; i++) mx = fmaxf(mx, v[i]);
        mx = fmaxf(mx, __shfl_xor_sync(0xFFFFFFFFu, mx, 1));
        mx = fmaxf(mx, __shfl_xor_sync(0xFFFFFFFFu, mx, 2));
        float s = 0.0f;
#pragma unroll
        for (int i = 0; i < 8; i++) { v[i] = __expf(v[i] - mx); s += v[i]; }
        s += __shfl_xor_sync(0xFFFFFFFFu, s, 1);
        s += __shfl_xor_sync(0xFFFFFFFFu, s, 2);
        float is = 1.0f / s;
#pragma unroll
        for (int nt = 0; nt < 4; nt++) {
            float sa0 = v[2*nt] * is, sa1 = v[2*nt+1] * is;
            csv[2*nt] += sa0; csv[2*nt+1] += sa1;
            *(float2*)&g_sb[(size_t)(bm0 + r) * 32 + 8*nt + 2*q] =
                make_float2(sa0 * inv, sa1 * inv);
        }
    }
    // colsum reduce over g-groups, then shared atomics
#pragma unroll
    for (int i = 0; i < 8; i++) {
        float v = csv[i];
        v += __shfl_xor_sync(0xFFFFFFFFu, v, 4);
        v += __shfl_xor_sync(0xFFFFFFFFu, v, 8);
        v += __shfl_xor_sync(0xFFFFFFFFu, v, 16);
        if (g == 0) atomicAdd(&colsum_s[8 * (i >> 1) + 2 * q + (i & 1)], v);
    }
    __syncthreads();
    if (t < 32) atomicAdd(&g_colsum[b * 32 + t], colsum_s[t]);
}

// ---------------------------------------------------------------------------
// Kernel G: agg[b] = sb[b]^T @ x[b]  ([32,512]x[512,2048]), tensor cores.
// C rows = clusters (2 m16 tiles), cols = d tile 128 (16 n8 tiles).
// Warp (w&1) -> cluster half, (w>>1) -> 32-d quarter. m chunk 64 tokens.
// A via ldmatrix.trans from Ss[m][k] (stride 56), B via trans from Xs[m][d].
// Epilogue: vlad = agg - colsum*cent, write out, accumulate nrmsq.
// ---------------------------------------------------------------------------
__global__ __launch_bounds__(256) void agg_kernel(
    const float* __restrict__ x, const float* __restrict__ cent,
    float* __restrict__ out)
{
    __shared__ __align__(16) __nv_bfloat16 Xs[2][64 * 128];  // [m][d] swizzled
    __shared__ __align__(16) __nv_bfloat16 Ss[2][64 * 56];   // [m][k], stride 56

    const int t = threadIdx.x, lane = t & 31, w = t >> 5;
    const int b  = blockIdx.x >> 4;
    const int d0 = (blockIdx.x & 15) * 128;

    float C[4][4];
#pragma unroll
    for (int i = 0; i < 4; i++)
#pragma unroll
        for (int j = 0; j < 4; j++) C[i][j] = 0.0f;

    const int xu = t & 15, xr0 = t >> 4;
    const int clb = 16 * (w & 1);
    const int dwb = 32 * (w >> 1);

    for (int m0 = 0; m0 < 512; m0 += 64) {
        // stage x -> hi/lo bf16 [m][d] first (DRAM loads, front-batched)
#pragma unroll
        for (int i = 0; i < 4; i++) {
            int r = xr0 + 16 * i;
            const float4* p = (const float4*)(x + (size_t)(b * 512 + m0 + r) * 2048 + d0 + xu * 8);
            float4 f0 = p[0], f1 = p[1];
            uint4 H, L; split8(f0, f1, H, L);
            int off = r * 128 + ((xu ^ (r & 7)) << 3);
            *(uint4*)&Xs[0][off] = H;
            *(uint4*)&Xs[1][off] = L;
        }
        // stage sb -> hi/lo bf16 [m][k] (L2-resident, overlaps behind x)
#pragma unroll
        for (int i = 0; i < 2; i++) {
            int idx = t + 256 * i;
            int m = idx >> 3, kq = (idx & 7) * 4;
            float4 f = *(const float4*)&g_sb[(size_t)(b * 512 + m0 + m) * 32 + kq];
            __nv_bfloat162 h01 = __floats2bfloat162_rn(f.x, f.y);
            __nv_bfloat162 h23 = __floats2bfloat162_rn(f.z, f.w);
            __nv_bfloat162 l01 = __floats2bfloat162_rn(f.x - __low2float(h01),
                                                       f.y - __high2float(h01));
            __nv_bfloat162 l23 = __floats2bfloat162_rn(f.z - __low2float(h23),
                                                       f.w - __high2float(h23));
            *(uint2*)&Ss[0][m * 56 + kq] =
                make_uint2(*(uint32_t*)&h01, *(uint32_t*)&h23);
            *(uint2*)&Ss[1][m * 56 + kq] =
                make_uint2(*(uint32_t*)&l01, *(uint32_t*)&l23);
        }
        __syncthreads();

#pragma unroll
        for (int kk = 0; kk < 64; kk += 16) {
            uint32_t ah[4], al[4], bh[8], bl[8];
            {   // A fragments (trans): stored [tok][cl] -> eff [cl][tok]
                int tok = kk + (lane & 7) + ((lane >> 4) << 3);
                int cl  = clb + ((lane >> 3) & 1) * 8;
                int off = tok * 56 + cl;
                ldmx4t(ah, s2u(&Ss[0][off]));
                ldmx4t(al, s2u(&Ss[1][off]));
            }
            {   // B fragments (trans): stored [tok][d] -> eff [d][tok]
                int tok = kk + (lane & 7) + ((lane >> 3) & 1) * 8;
#pragma unroll
                for (int half = 0; half < 2; half++) {
                    int du = (dwb >> 3) + 2 * half + (lane >> 4);
                    int off = tok * 128 + ((du ^ (tok & 7)) << 3);
                    ldmx4t(bh + 4 * half, s2u(&Xs[0][off]));
                    ldmx4t(bl + 4 * half, s2u(&Xs[1][off]));
                }
            }
#pragma unroll
            for (int nt = 0; nt < 4; nt++) {
                mma16816(C[nt], ah, bh[2*nt], bh[2*nt+1]);
                mma16816(C[nt], ah, bl[2*nt], bl[2*nt+1]);
                mma16816(C[nt], al, bh[2*nt], bh[2*nt+1]);
            }
        }
        __syncthreads();
    }

    // epilogue
    const int g = lane >> 2, q = lane & 3;
#pragma unroll
    for (int idx = 0; idx < 2; idx++) {
        int kr = clb + g + 8 * idx;
        float csk = g_colsum[b * 32 + kr];
        float ssq = 0.0f;
#pragma unroll
        for (int nt = 0; nt < 4; nt++) {
            int d = d0 + dwb + 8 * nt + 2 * q;
            float2 cv = *(const float2*)&cent[(size_t)kr * 2048 + d];
            float o0 = C[nt][2*idx]   - csk * cv.x;
            float o1 = C[nt][2*idx+1] - csk * cv.y;
            *(float2*)&out[((size_t)b * 32 + kr) * 2048 + d] = make_float2(o0, o1);
            ssq += o0 * o0 + o1 * o1;
        }
        ssq += __shfl_xor_sync(0xFFFFFFFFu, ssq, 1);
        ssq += __shfl_xor_sync(0xFFFFFFFFu, ssq, 2);
        if (q == 0) atomicAdd(&g_nrmsq[b * 32 + kr], ssq);
    }
}

// ---------------------------------------------------------------------------
// F1: per-(b,k) final scale = 1/(max(||v_k||,eps) * max(||flat intra-norm||,eps))
// ---------------------------------------------------------------------------
__global__ void factor_kernel() {
    int b = blockIdx.x;
    int k = threadIdx.x;   // 32 threads
    float nsq = g_nrmsq[b * cK + k];
    float n   = sqrtf(nsq);
    float dn  = fmaxf(n, 1e-12f);
    float r   = n / dn;
    float g2  = r * r;
#pragma unroll
    for (int o = 1; o < 32; o <<= 1) g2 += __shfl_xor_sync(0xFFFFFFFFu, g2, o);
    float g = sqrtf(g2);
    g_factor[b * cK + k] = 1.0f / (dn * fmaxf(g, 1e-12f));
}

// ---------------------------------------------------------------------------
// F2: in-place scale of out by per-(b,k) factor
// ---------------------------------------------------------------------------
__global__ __launch_bounds__(256) void scale_kernel(float* __restrict__ out) {
    int i = blockIdx.x * 256 + threadIdx.x;   // float4 index; total 1048576
    float4* o4 = (float4*)out;
    float f = g_factor[i >> 9];               // 512 float4 per (b,k)
    float4 v = o4[i];
    v.x *= f; v.y *= f; v.z *= f; v.w *= f;
    o4[i] = v;
}

// ---------------------------------------------------------------------------
extern "C" void kernel_launch(void* const* d_in, const int* in_sizes, int n_in,
                              void* d_out, int out_size) {
    const float* x    = (const float*)d_in[0];
    const float* Wm   = (const float*)d_in[1];
    const float* cent = (const float*)d_in[2];
    float* out        = (float*)d_out;

    init_kernel<<<8, 256>>>();
    logits_kernel<<<cBM / 128, 256>>>(x, Wm);
    agg_kernel<<<cB * 16, 256>>>(x, cent, out);
    factor_kernel<<<cB, 32>>>();
    scale_kernel<<<(cB * cK * cD / 4) / 256, 256>>>(out);
}